// round 15
// baseline (speedup 1.0000x reference)
#include <cuda_runtime.h>
#include <cuda_fp16.h>
#include <math.h>
#include <stdint.h>

// Problem constants
#define NH   2
#define DKH  96
#define D    192
#define T    4096
#define B    16
#define BANK 1000

// Scratch (static device allocations)
__device__ __half    g_q16[B * T * D];        // scaled Q, [b][t][d] fp16
__device__ __half    g_attn16[B * T * D];     // attention out pre-Wo, [b][t][d] fp16
__device__ __half    g_k16T[NH * BANK * DKH]; // K, [h][s][dk] fp16
__device__ __half    g_v16[NH * DKH * BANK];  // V, [h][dk][s] fp16
__device__ uint32_t  g_Wq16[D * (D / 2)];     // alpha_q * Wq, [o][k2] h2
__device__ uint32_t  g_Wo16[D * (D / 2)];     // Wo, [o][k2] h2
__device__ float     g_bq[D];                 // alpha_q * bq

__device__ __forceinline__ float ex2f(float x) {
    float r; asm("ex2.approx.ftz.f32 %0, %1;" : "=f"(r) : "f"(x)); return r;
}
__device__ __forceinline__ uint32_t h2bits(float a, float b) {
    __half2 h = __floats2half2_rn(a, b);
    return *(uint32_t*)&h;
}
__device__ __forceinline__ uint32_t smem_addr32(const void* p) {
    return (uint32_t)__cvta_generic_to_shared(p);
}
__device__ __forceinline__ void mma16(float d[4],
                                      const uint32_t a[4],
                                      uint32_t b0, uint32_t b1) {
    asm volatile("mma.sync.aligned.m16n8k16.row.col.f32.f16.f16.f32 "
                 "{%0,%1,%2,%3}, {%4,%5,%6,%7}, {%8,%9}, {%0,%1,%2,%3};"
                 : "+f"(d[0]), "+f"(d[1]), "+f"(d[2]), "+f"(d[3])
                 : "r"(a[0]), "r"(a[1]), "r"(a[2]), "r"(a[3]), "r"(b0), "r"(b1));
}
__device__ __forceinline__ void ldmx4(uint32_t r[4], uint32_t addr) {
    asm volatile("ldmatrix.sync.aligned.m8n8.x4.shared.b16 {%0,%1,%2,%3}, [%4];"
                 : "=r"(r[0]), "=r"(r[1]), "=r"(r[2]), "=r"(r[3]) : "r"(addr));
}
__device__ __forceinline__ void stmx4(uint32_t addr, uint32_t r0, uint32_t r1,
                                      uint32_t r2, uint32_t r3) {
    asm volatile("stmatrix.sync.aligned.m8n8.x4.shared.b16 [%0], {%1,%2,%3,%4};"
                 :: "r"(addr), "r"(r0), "r"(r1), "r"(r2), "r"(r3) : "memory");
}
__device__ __forceinline__ void cpasync16z(uint32_t dst, const void* src, int srcbytes) {
    asm volatile("cp.async.cg.shared.global [%0], [%1], 16, %2;"
                 :: "r"(dst), "l"(src), "r"(srcbytes) : "memory");
}
__device__ __forceinline__ void cpasync16(uint32_t dst, const void* src) {
    asm volatile("cp.async.cg.shared.global [%0], [%1], 16;"
                 :: "r"(dst), "l"(src) : "memory");
}
__device__ __forceinline__ void cp_commit() {
    asm volatile("cp.async.commit_group;" ::: "memory");
}
__device__ __forceinline__ void cp_wait_all() {
    asm volatile("cp.async.wait_group 0;" ::: "memory");
}
__device__ __forceinline__ void bar_pair(int id) {
    asm volatile("bar.sync %0, 64;" :: "r"(id) : "memory");
}

// ---------------------------------------------------------------------------
// Kernel 0: weight prep. Converts Wq (scaled by alpha_q) and Wo to fp16 h2.
// ---------------------------------------------------------------------------
__global__ void wprep_kernel(const float* __restrict__ Wq, const float* __restrict__ bq,
                             const float* __restrict__ Wo, float alpha_q) {
    int which = blockIdx.x;
    const float* W = which ? Wo : Wq;
    uint32_t*  W16 = which ? g_Wo16 : g_Wq16;
    float alpha = which ? 1.0f : alpha_q;
    for (int i = threadIdx.x; i < D * (D / 2); i += 256) {
        int o = i / (D / 2), k2 = i % (D / 2);
        W16[o * (D / 2) + k2] = h2bits(alpha * W[o * D + 2 * k2],
                                       alpha * W[o * D + 2 * k2 + 1]);
    }
    if (which == 0)
        for (int i = threadIdx.x; i < D; i += 256) g_bq[i] = alpha_q * bq[i];
}

// ---------------------------------------------------------------------------
// Kernel 1: K/V projection of memory bank (batch-independent) -> fp16.
// ---------------------------------------------------------------------------
__global__ void __launch_bounds__(256) kv_proj_kernel(
        const float* __restrict__ mb,
        const float* __restrict__ Wk, const float* __restrict__ bk,
        const float* __restrict__ Wv, const float* __restrict__ bv) {
    __shared__ float wks[4][192];
    __shared__ float wvs[4][192];

    int s   = blockIdx.x * 256 + threadIdx.x;
    int dk0 = blockIdx.y * 4;
    int h   = blockIdx.z;
    int row0 = h * DKH + dk0;

    for (int i = threadIdx.x; i < 4 * 192; i += 256) {
        int j = i / 192, c = i % 192;
        wks[j][c] = Wk[(row0 + j) * D + c];
        wvs[j][c] = Wv[(row0 + j) * D + c];
    }
    __syncthreads();
    if (s >= BANK) return;

    float ak[4] = {0.f, 0.f, 0.f, 0.f};
    float av[4] = {0.f, 0.f, 0.f, 0.f};
    #pragma unroll 4
    for (int c = 0; c < D; c++) {
        float x = mb[c * BANK + s];
        #pragma unroll
        for (int j = 0; j < 4; j++) {
            ak[j] = fmaf(wks[j][c], x, ak[j]);
            av[j] = fmaf(wvs[j][c], x, av[j]);
        }
    }
    __half hk[4];
    #pragma unroll
    for (int j = 0; j < 4; j++) {
        hk[j] = __float2half_rn(ak[j] + bk[row0 + j]);
        g_v16[((size_t)h * DKH + dk0 + j) * BANK + s] = __float2half_rn(av[j] + bv[row0 + j]);
    }
    *(uint2*)&g_k16T[((size_t)h * BANK + s) * DKH + dk0] = *(uint2*)hk;
}

// ---------------------------------------------------------------------------
// Kernel 2/4: channel projection, fp16 m16n8k16 + ldmatrix, 512 threads.
// ---------------------------------------------------------------------------
#define PJP2 100
#define FBP  132
#define SMEM_PROJ_BYTES ((192 * PJP2 + 128 * PJP2) * 4)

__global__ void __launch_bounds__(512) proj16_kernel(
        const uint32_t* __restrict__ W16, const float* __restrict__ bias,
        const float* __restrict__ Xf, int src_half,
        float* __restrict__ Yf, int dst_half) {
    extern __shared__ uint32_t ps[];
    uint32_t* Ws2 = ps;                 // 192*100 words
    uint32_t* Xs2 = ps + 192 * PJP2;    // 128*100 words
    float*    fbuf = (float*)ps;        // epilogue: [192][FBP] floats

    int tid  = threadIdx.x;
    int lane = tid & 31;
    int warp = tid >> 5;
    int g    = lane >> 2;
    int tg   = lane & 3;
    int wm   = warp >> 2;   // t: 32 each (0..3)
    int wn   = warp & 3;    // o: 48 each

    int b  = blockIdx.z;
    int t0 = blockIdx.x * 128;
    const float* Xb = Xf + (size_t)b * D * T;
    const __half* Ab = g_attn16 + (size_t)b * T * D;

    uint32_t sb = smem_addr32(ps);

    #pragma unroll
    for (int it = 0; it < 9; it++) {
        int i = tid + it * 512;
        int o = i / 24, c = i % 24;
        cpasync16(sb + 4u * (o * PJP2 + c * 4), W16 + o * 96 + c * 4);
    }
    if (src_half == 0) {
        #pragma unroll
        for (int it = 0; it < 6; it++) {
            int i = tid + it * 512;
            int k2 = i >> 5, t4 = i & 31;
            float4 xa = *(const float4*)(Xb + (size_t)(2 * k2)     * T + t0 + t4 * 4);
            float4 xb = *(const float4*)(Xb + (size_t)(2 * k2 + 1) * T + t0 + t4 * 4);
            Xs2[(t4 * 4 + 0) * PJP2 + k2] = h2bits(xa.x, xb.x);
            Xs2[(t4 * 4 + 1) * PJP2 + k2] = h2bits(xa.y, xb.y);
            Xs2[(t4 * 4 + 2) * PJP2 + k2] = h2bits(xa.z, xb.z);
            Xs2[(t4 * 4 + 3) * PJP2 + k2] = h2bits(xa.w, xb.w);
        }
    } else {
        #pragma unroll
        for (int it = 0; it < 6; it++) {
            int i = tid + it * 512;
            int t = i / 24, c = i % 24;
            cpasync16(sb + 4u * (192 * PJP2 + t * PJP2 + c * 4),
                      Ab + (size_t)(t0 + t) * D + c * 8);
        }
    }
    cp_commit();
    cp_wait_all();
    __syncthreads();

    int a_row = lane & 15;
    int a_kw  = 4 * ((lane >> 4) & 1);
    int b_row = 8 * ((lane >> 4) & 1) + (lane & 7);
    int b_kw  = 4 * ((lane >> 3) & 1);

    uint32_t xa_addr[2], wb_addr[3];
    #pragma unroll
    for (int mt = 0; mt < 2; mt++)
        xa_addr[mt] = sb + 4 * (192 * PJP2 + (wm * 32 + mt * 16 + a_row) * PJP2 + a_kw);
    #pragma unroll
    for (int np = 0; np < 3; np++)
        wb_addr[np] = sb + 4 * ((wn * 48 + np * 16 + b_row) * PJP2 + b_kw);

    float acc[2][6][4];
    #pragma unroll
    for (int mt = 0; mt < 2; mt++)
        #pragma unroll
        for (int nt = 0; nt < 6; nt++)
            #pragma unroll
            for (int c = 0; c < 4; c++) acc[mt][nt][c] = 0.f;

    #pragma unroll
    for (int ks = 0; ks < 12; ks++) {
        uint32_t koff = ks * 32;
        uint32_t aX[2][4], bw[3][4];
        #pragma unroll
        for (int mt = 0; mt < 2; mt++) ldmx4(aX[mt], xa_addr[mt] + koff);
        #pragma unroll
        for (int np = 0; np < 3; np++) ldmx4(bw[np], wb_addr[np] + koff);
        #pragma unroll
        for (int mt = 0; mt < 2; mt++)
            #pragma unroll
            for (int np = 0; np < 3; np++) {
                mma16(acc[mt][np * 2],     aX[mt], bw[np][0], bw[np][1]);
                mma16(acc[mt][np * 2 + 1], aX[mt], bw[np][2], bw[np][3]);
            }
    }

    if (dst_half) {
        #pragma unroll
        for (int mt = 0; mt < 2; mt++) {
            int t_lo = wm * 32 + mt * 16 + g;
            int t_hi = t_lo + 8;
            #pragma unroll
            for (int nt = 0; nt < 6; nt++) {
                int o0 = wn * 48 + nt * 8 + 2 * tg;
                float b0v = bias[o0], b1v = bias[o0 + 1];
                *(uint32_t*)&g_q16[((size_t)b * T + t0 + t_lo) * D + o0] =
                    h2bits(acc[mt][nt][0] + b0v, acc[mt][nt][1] + b1v);
                *(uint32_t*)&g_q16[((size_t)b * T + t0 + t_hi) * D + o0] =
                    h2bits(acc[mt][nt][2] + b0v, acc[mt][nt][3] + b1v);
            }
        }
    } else {
        __syncthreads();
        #pragma unroll
        for (int mt = 0; mt < 2; mt++) {
            int t_lo = wm * 32 + mt * 16 + g;
            int t_hi = t_lo + 8;
            #pragma unroll
            for (int nt = 0; nt < 6; nt++) {
                int o0 = wn * 48 + nt * 8 + 2 * tg;
                float b0v = bias[o0], b1v = bias[o0 + 1];
                fbuf[(o0)     * FBP + t_lo] = acc[mt][nt][0] + b0v;
                fbuf[(o0 + 1) * FBP + t_lo] = acc[mt][nt][1] + b1v;
                fbuf[(o0)     * FBP + t_hi] = acc[mt][nt][2] + b0v;
                fbuf[(o0 + 1) * FBP + t_hi] = acc[mt][nt][3] + b1v;
            }
        }
        __syncthreads();
        #pragma unroll
        for (int it = 0; it < 12; it++) {
            int i = tid + it * 512;
            int o = i >> 5, t4 = i & 31;
            float4 v = *(float4*)&fbuf[o * FBP + t4 * 4];
            *(float4*)(Yf + ((size_t)b * D + o) * T + t0 + t4 * 4) = v;
        }
    }
}

// ---------------------------------------------------------------------------
// Kernel 3: fp16 mma.sync attention, no-max softmax, ldmatrix/stmatrix,
// cp.async double-buffered K/V; softmax->PV sync is now a PAIRWISE named
// barrier (P is pair-private), de-aligning phases so one pair's PV MMAs
// overlap another pair's MUFU softmax. BANK mask only on ci==7, hf==3.
// ---------------------------------------------------------------------------
#define QROWS 256
#define SCH   128
#define QP2   52
#define KP2   52
#define VP2   68
#define PP2   68
#define KSZ   (SCH * KP2)              // 6656
#define VSZ   (DKH * VP2)              // 6528
#define OQ2   0
#define OK2   (QROWS * QP2)            // 13312 (buf0); buf1 at +KSZ
#define OV2   (OK2 + 2 * KSZ)          // 26624 (buf0); buf1 at +VSZ
#define OP2   (OV2 + 2 * VSZ)          // 39680
#define OL2   (OP2 + QROWS * PP2)      // 57088
#define SMEM_ATTN_BYTES ((OL2 + 2 * QROWS) * 4)   // 230400

__global__ void __launch_bounds__(512, 1) attn_mma_kernel() {
    extern __shared__ uint32_t sh2[];
    float* lsh = (float*)(sh2 + OL2);

    int tid  = threadIdx.x;
    int lane = tid & 31;
    int warp = tid >> 5;
    int g    = lane >> 2;
    int tg   = lane & 3;
    int wqi  = warp >> 1;
    int wsi  = warp & 1;
    int wq   = wqi * 32;
    int bar_id = 1 + wqi;   // named barrier per q-pair (ids 1..8)

    int t0 = blockIdx.x * QROWS;
    int h  = blockIdx.y;
    int b  = blockIdx.z;

    uint32_t sb = smem_addr32(sh2);
    const __half* kb = g_k16T + (size_t)h * BANK * DKH;
    const __half* vb = g_v16 + (size_t)h * DKH * BANK;

    auto stage_kv = [&](int cin) {
        int s0c2 = cin * SCH;
        int valid2 = BANK - s0c2; if (valid2 > SCH) valid2 = SCH;
        uint32_t kdst = sb + 4u * (OK2 + (cin & 1) * KSZ);
        uint32_t vdst = sb + 4u * (OV2 + (cin & 1) * VSZ);
        #pragma unroll
        for (int it = 0; it < 3; it++) {
            int i = tid + it * 512;
            int row = i / 12, c = i % 12;
            int ok = row < valid2;
            const __half* src = kb + (size_t)(s0c2 + (ok ? row : 0)) * DKH + c * 8;
            cpasync16z(kdst + 4u * (row * KP2 + c * 4), src, ok ? 16 : 0);
        }
        #pragma unroll
        for (int it = 0; it < 3; it++) {
            int i = tid + it * 512;
            int row = i >> 4, c = i & 15;
            int ok = (c * 8 + 8) <= valid2;
            const __half* src = vb + (size_t)row * BANK + s0c2 + (ok ? c * 8 : 0);
            cpasync16z(vdst + 4u * (row * VP2 + c * 4), src, ok ? 16 : 0);
        }
        cp_commit();
    };

    stage_kv(0);
    const __half* qb = g_q16 + ((size_t)b * T + t0) * D + h * DKH;
    for (int i = tid; i < 3072; i += 512) {
        int q = i / 12, c = i % 12;
        uint4 v = *(const uint4*)(qb + (size_t)q * D + c * 8);
        *(uint4*)&sh2[OQ2 + q * QP2 + c * 4] = v;
    }

    int a_row  = lane & 15;
    int a_kw   = 4 * ((lane >> 4) & 1);
    int b_row  = 8 * ((lane >> 4) & 1) + (lane & 7);
    int b_kw   = 4 * ((lane >> 3) & 1);
    int st_row = 8 * ((lane >> 3) & 1) + (lane & 7);
    int st_cw  = 4 * ((lane >> 4) & 1);

    uint32_t qa_addr[2], pa_addr[2], ps_addr[2];
    #pragma unroll
    for (int mt = 0; mt < 2; mt++) {
        qa_addr[mt] = sb + 4 * (OQ2 + (wq + mt * 16 + a_row)  * QP2 + a_kw);
        pa_addr[mt] = sb + 4 * (OP2 + (wq + mt * 16 + a_row)  * PP2 + a_kw);
        ps_addr[mt] = sb + 4 * (OP2 + (wq + mt * 16 + st_row) * PP2 + st_cw);
    }
    uint32_t kb_addr0 = sb + 4 * (OK2 + b_row * KP2 + b_kw);
    uint32_t vb_addr0 = sb + 4 * (OV2 + (wsi * 48 + b_row) * VP2 + b_kw);

    float o[2][6][4];
    #pragma unroll
    for (int mt = 0; mt < 2; mt++)
        #pragma unroll
        for (int nt = 0; nt < 6; nt++)
            #pragma unroll
            for (int c = 0; c < 4; c++) o[mt][nt][c] = 0.f;
    float lsum[2][2] = {{0.f, 0.f}, {0.f, 0.f}};

    for (int ci = 0; ci < 8; ci++) {
        int s0c = ci * SCH;
        uint32_t kbuf = kb_addr0 + 4u * ((ci & 1) * KSZ);
        uint32_t vbuf = vb_addr0 + 4u * ((ci & 1) * VSZ);

        cp_wait_all();
        __syncthreads();   // K/V(ci) ready; all PV(ci-1) complete

        if (ci < 7) stage_kv(ci + 1);

        // ---- QK + softmax: this warp's two 32-col quarters ----
        #pragma unroll
        for (int hq = 0; hq < 2; hq++) {
            int hf = 2 * wsi + hq;
            float sc[2][4][4];
            #pragma unroll
            for (int mt = 0; mt < 2; mt++)
                #pragma unroll
                for (int nt = 0; nt < 4; nt++)
                    #pragma unroll
                    for (int c = 0; c < 4; c++) sc[mt][nt][c] = 0.f;

            #pragma unroll
            for (int ks = 0; ks < 6; ks++) {
                uint32_t koff = ks * 32;
                uint32_t aQ[2][4];
                ldmx4(aQ[0], qa_addr[0] + koff);
                ldmx4(aQ[1], qa_addr[1] + koff);
                #pragma unroll
                for (int np = 0; np < 2; np++) {
                    uint32_t bk4[4];
                    ldmx4(bk4, kbuf + 4 * (uint32_t)((hf * 32 + np * 16) * KP2) + koff);
                    mma16(sc[0][np * 2],     aQ[0], bk4[0], bk4[1]);
                    mma16(sc[0][np * 2 + 1], aQ[0], bk4[2], bk4[3]);
                    mma16(sc[1][np * 2],     aQ[1], bk4[0], bk4[1]);
                    mma16(sc[1][np * 2 + 1], aQ[1], bk4[2], bk4[3]);
                }
            }

            // exp (no max); BANK mask only for the final quarter of chunk 7
            if (ci == 7 && hf == 3) {
                #pragma unroll
                for (int mt = 0; mt < 2; mt++) {
                    #pragma unroll
                    for (int nt = 0; nt < 4; nt++) {
                        int sg = s0c + hf * 32 + nt * 8 + 2 * tg;
                        float p0 = (sg     < BANK) ? ex2f(sc[mt][nt][0]) : 0.f;
                        float p1 = (sg + 1 < BANK) ? ex2f(sc[mt][nt][1]) : 0.f;
                        float p2 = (sg     < BANK) ? ex2f(sc[mt][nt][2]) : 0.f;
                        float p3 = (sg + 1 < BANK) ? ex2f(sc[mt][nt][3]) : 0.f;
                        lsum[mt][0] += p0 + p1;
                        lsum[mt][1] += p2 + p3;
                        sc[mt][nt][0] = p0; sc[mt][nt][1] = p1;
                        sc[mt][nt][2] = p2; sc[mt][nt][3] = p3;
                    }
                }
            } else {
                #pragma unroll
                for (int mt = 0; mt < 2; mt++) {
                    #pragma unroll
                    for (int nt = 0; nt < 4; nt++) {
                        float p0 = ex2f(sc[mt][nt][0]);
                        float p1 = ex2f(sc[mt][nt][1]);
                        float p2 = ex2f(sc[mt][nt][2]);
                        float p3 = ex2f(sc[mt][nt][3]);
                        lsum[mt][0] += p0 + p1;
                        lsum[mt][1] += p2 + p3;
                        sc[mt][nt][0] = p0; sc[mt][nt][1] = p1;
                        sc[mt][nt][2] = p2; sc[mt][nt][3] = p3;
                    }
                }
            }
            #pragma unroll
            for (int mt = 0; mt < 2; mt++) {
                #pragma unroll
                for (int np = 0; np < 2; np++) {
                    stmx4(ps_addr[mt] + 4 * (uint32_t)(hf * 16 + np * 8),
                          h2bits(sc[mt][np * 2][0],     sc[mt][np * 2][1]),
                          h2bits(sc[mt][np * 2][2],     sc[mt][np * 2][3]),
                          h2bits(sc[mt][np * 2 + 1][0], sc[mt][np * 2 + 1][1]),
                          h2bits(sc[mt][np * 2 + 1][2], sc[mt][np * 2 + 1][3]));
                }
            }
        }
        bar_pair(bar_id);   // P complete within this q-pair only

        // ---- PV: O[q][dk_half] += P[q][s] * V[dk][s] over full chunk ----
        #pragma unroll
        for (int ks = 0; ks < 8; ks++) {
            uint32_t koff = ks * 32;
            uint32_t aP[2][4];
            ldmx4(aP[0], pa_addr[0] + koff);
            ldmx4(aP[1], pa_addr[1] + koff);
            #pragma unroll
            for (int np = 0; np < 3; np++) {
                uint32_t bv4[4];
                ldmx4(bv4, vbuf + 4 * (uint32_t)(np * 16 * VP2) + koff);
                mma16(o[0][np * 2],     aP[0], bv4[0], bv4[1]);
                mma16(o[0][np * 2 + 1], aP[0], bv4[2], bv4[3]);
                mma16(o[1][np * 2],     aP[1], bv4[0], bv4[1]);
                mma16(o[1][np * 2 + 1], aP[1], bv4[2], bv4[3]);
            }
        }
    }

    // ---- Reduce l within quad, publish per-half, combine across pair ----
    #pragma unroll
    for (int mt = 0; mt < 2; mt++)
        #pragma unroll
        for (int j = 0; j < 2; j++) {
            float v = lsum[mt][j];
            v += __shfl_xor_sync(0xFFFFFFFF, v, 1);
            v += __shfl_xor_sync(0xFFFFFFFF, v, 2);
            lsum[mt][j] = v;
        }
    __syncthreads();
    if (tg == 0) {
        #pragma unroll
        for (int mt = 0; mt < 2; mt++) {
            lsh[wsi * QROWS + wq + mt * 16 + g]     = lsum[mt][0];
            lsh[wsi * QROWS + wq + mt * 16 + g + 8] = lsum[mt][1];
        }
    }
    __syncthreads();

    float inv[2][2];
    #pragma unroll
    for (int mt = 0; mt < 2; mt++) {
        int q_lo = wq + mt * 16 + g;
        inv[mt][0] = 1.f / (lsh[q_lo]     + lsh[QROWS + q_lo]);
        inv[mt][1] = 1.f / (lsh[q_lo + 8] + lsh[QROWS + q_lo + 8]);
    }

    __half* ob = g_attn16 + ((size_t)b * T + t0) * D + h * DKH;
    #pragma unroll
    for (int mt = 0; mt < 2; mt++) {
        int q_lo = wq + mt * 16 + g;
        int q_hi = q_lo + 8;
        #pragma unroll
        for (int nt = 0; nt < 6; nt++) {
            int dk = wsi * 48 + nt * 8 + 2 * tg;
            *(uint32_t*)(ob + (size_t)q_lo * D + dk) =
                h2bits(o[mt][nt][0] * inv[mt][0], o[mt][nt][1] * inv[mt][0]);
            *(uint32_t*)(ob + (size_t)q_hi * D + dk) =
                h2bits(o[mt][nt][2] * inv[mt][1], o[mt][nt][3] * inv[mt][1]);
        }
    }
}

// ---------------------------------------------------------------------------
extern "C" void kernel_launch(void* const* d_in, const int* in_sizes, int n_in,
                              void* d_out, int out_size) {
    const float* z  = (const float*)d_in[0];
    const float* mb = (const float*)d_in[1];
    const float* Wq = (const float*)d_in[2];
    const float* bq = (const float*)d_in[3];
    const float* Wk = (const float*)d_in[4];
    const float* bk = (const float*)d_in[5];
    const float* Wv = (const float*)d_in[6];
    const float* bv = (const float*)d_in[7];
    const float* Wo = (const float*)d_in[8];
    const float* bo = (const float*)d_in[9];
    float* out = (float*)d_out;

    const float alpha_q = 1.4426950408889634f / sqrtf(96.0f);

    // 0. Weight prep (fp16 conversion, alpha folded into Wq/bq)
    wprep_kernel<<<2, 256>>>(Wq, bq, Wo, alpha_q);

    // 1. K/V projection (batch-independent) -> fp16
    kv_proj_kernel<<<dim3(4, 24, 2), 256>>>(mb, Wk, bk, Wv, bv);

    uint32_t *dWq16, *dWo16; float* dbq;
    cudaGetSymbolAddress((void**)&dWq16, g_Wq16);
    cudaGetSymbolAddress((void**)&dWo16, g_Wo16);
    cudaGetSymbolAddress((void**)&dbq,  g_bq);

    // 2. Q projection -> g_q16 [b][t][d] fp16
    cudaFuncSetAttribute(proj16_kernel,
                         cudaFuncAttributeMaxDynamicSharedMemorySize, SMEM_PROJ_BYTES);
    proj16_kernel<<<dim3(32, 1, 16), 512, SMEM_PROJ_BYTES>>>(
        dWq16, dbq, z, 0, nullptr, 1);

    // 3. fp16 mma.sync attention (pairwise-barrier pipelined) -> g_attn16
    cudaFuncSetAttribute(attn_mma_kernel,
                         cudaFuncAttributeMaxDynamicSharedMemorySize, SMEM_ATTN_BYTES);
    attn_mma_kernel<<<dim3(T / QROWS, NH, B), 512, SMEM_ATTN_BYTES>>>();

    // 4. Output projection -> d_out fp32 [b][d][t]
    proj16_kernel<<<dim3(32, 1, 16), 512, SMEM_PROJ_BYTES>>>(
        dWo16, bo, nullptr, 1, out, 0);
}

// round 17
// speedup vs baseline: 1.0569x; 1.0569x over previous
#include <cuda_runtime.h>
#include <cuda_fp16.h>
#include <math.h>
#include <stdint.h>

// Problem constants
#define NH   2
#define DKH  96
#define D    192
#define T    4096
#define B    16
#define BANK 1000

// Scratch (static device allocations)
__device__ __half    g_q16[B * T * D];        // scaled Q, [b][t][d] fp16
__device__ __half    g_attn16[B * T * D];     // attention out pre-Wo, [b][t][d] fp16
__device__ __half    g_k16T[NH * BANK * DKH]; // K, [h][s][dk] fp16
__device__ __half    g_v16[NH * DKH * BANK];  // V, [h][dk][s] fp16
__device__ uint32_t  g_Wq16[D * (D / 2)];     // alpha_q * Wq, [o][k2] h2
__device__ uint32_t  g_Wo16[D * (D / 2)];     // Wo, [o][k2] h2
__device__ float     g_bq[D];                 // alpha_q * bq

__device__ __forceinline__ float ex2f(float x) {
    float r; asm("ex2.approx.ftz.f32 %0, %1;" : "=f"(r) : "f"(x)); return r;
}
__device__ __forceinline__ uint32_t h2bits(float a, float b) {
    __half2 h = __floats2half2_rn(a, b);
    return *(uint32_t*)&h;
}
__device__ __forceinline__ uint32_t smem_addr32(const void* p) {
    return (uint32_t)__cvta_generic_to_shared(p);
}
__device__ __forceinline__ void mma16(float d[4],
                                      const uint32_t a[4],
                                      uint32_t b0, uint32_t b1) {
    asm volatile("mma.sync.aligned.m16n8k16.row.col.f32.f16.f16.f32 "
                 "{%0,%1,%2,%3}, {%4,%5,%6,%7}, {%8,%9}, {%0,%1,%2,%3};"
                 : "+f"(d[0]), "+f"(d[1]), "+f"(d[2]), "+f"(d[3])
                 : "r"(a[0]), "r"(a[1]), "r"(a[2]), "r"(a[3]), "r"(b0), "r"(b1));
}
__device__ __forceinline__ void ldmx4(uint32_t r[4], uint32_t addr) {
    asm volatile("ldmatrix.sync.aligned.m8n8.x4.shared.b16 {%0,%1,%2,%3}, [%4];"
                 : "=r"(r[0]), "=r"(r[1]), "=r"(r[2]), "=r"(r[3]) : "r"(addr));
}
__device__ __forceinline__ void stmx4(uint32_t addr, uint32_t r0, uint32_t r1,
                                      uint32_t r2, uint32_t r3) {
    asm volatile("stmatrix.sync.aligned.m8n8.x4.shared.b16 [%0], {%1,%2,%3,%4};"
                 :: "r"(addr), "r"(r0), "r"(r1), "r"(r2), "r"(r3) : "memory");
}
__device__ __forceinline__ void cpasync16z(uint32_t dst, const void* src, int srcbytes) {
    asm volatile("cp.async.cg.shared.global [%0], [%1], 16, %2;"
                 :: "r"(dst), "l"(src), "r"(srcbytes) : "memory");
}
__device__ __forceinline__ void cpasync16(uint32_t dst, const void* src) {
    asm volatile("cp.async.cg.shared.global [%0], [%1], 16;"
                 :: "r"(dst), "l"(src) : "memory");
}
__device__ __forceinline__ void cp_commit() {
    asm volatile("cp.async.commit_group;" ::: "memory");
}
__device__ __forceinline__ void cp_wait_all() {
    asm volatile("cp.async.wait_group 0;" ::: "memory");
}
__device__ __forceinline__ void bar_pair(int id) {
    asm volatile("bar.sync %0, 64;" :: "r"(id) : "memory");
}

// ---------------------------------------------------------------------------
// Kernel 0: weight prep. Converts Wq (scaled by alpha_q) and Wo to fp16 h2.
// ---------------------------------------------------------------------------
__global__ void wprep_kernel(const float* __restrict__ Wq, const float* __restrict__ bq,
                             const float* __restrict__ Wo, float alpha_q) {
    int which = blockIdx.x;
    const float* W = which ? Wo : Wq;
    uint32_t*  W16 = which ? g_Wo16 : g_Wq16;
    float alpha = which ? 1.0f : alpha_q;
    for (int i = threadIdx.x; i < D * (D / 2); i += 256) {
        int o = i / (D / 2), k2 = i % (D / 2);
        W16[o * (D / 2) + k2] = h2bits(alpha * W[o * D + 2 * k2],
                                       alpha * W[o * D + 2 * k2 + 1]);
    }
    if (which == 0)
        for (int i = threadIdx.x; i < D; i += 256) g_bq[i] = alpha_q * bq[i];
}

// ---------------------------------------------------------------------------
// Kernel 1: K/V projection of memory bank (batch-independent) -> fp16.
// ---------------------------------------------------------------------------
__global__ void __launch_bounds__(256) kv_proj_kernel(
        const float* __restrict__ mb,
        const float* __restrict__ Wk, const float* __restrict__ bk,
        const float* __restrict__ Wv, const float* __restrict__ bv) {
    __shared__ float wks[4][192];
    __shared__ float wvs[4][192];

    int s   = blockIdx.x * 256 + threadIdx.x;
    int dk0 = blockIdx.y * 4;
    int h   = blockIdx.z;
    int row0 = h * DKH + dk0;

    for (int i = threadIdx.x; i < 4 * 192; i += 256) {
        int j = i / 192, c = i % 192;
        wks[j][c] = Wk[(row0 + j) * D + c];
        wvs[j][c] = Wv[(row0 + j) * D + c];
    }
    __syncthreads();
    if (s >= BANK) return;

    float ak[4] = {0.f, 0.f, 0.f, 0.f};
    float av[4] = {0.f, 0.f, 0.f, 0.f};
    #pragma unroll 4
    for (int c = 0; c < D; c++) {
        float x = mb[c * BANK + s];
        #pragma unroll
        for (int j = 0; j < 4; j++) {
            ak[j] = fmaf(wks[j][c], x, ak[j]);
            av[j] = fmaf(wvs[j][c], x, av[j]);
        }
    }
    __half hk[4];
    #pragma unroll
    for (int j = 0; j < 4; j++) {
        hk[j] = __float2half_rn(ak[j] + bk[row0 + j]);
        g_v16[((size_t)h * DKH + dk0 + j) * BANK + s] = __float2half_rn(av[j] + bv[row0 + j]);
    }
    *(uint2*)&g_k16T[((size_t)h * BANK + s) * DKH + dk0] = *(uint2*)hk;
}

// ---------------------------------------------------------------------------
// Kernel 2/4: channel projection, fp16 m16n8k16 + ldmatrix, 512 threads.
// (unchanged from R14)
// ---------------------------------------------------------------------------
#define PJP2 100
#define FBP  132
#define SMEM_PROJ_BYTES ((192 * PJP2 + 128 * PJP2) * 4)

__global__ void __launch_bounds__(512) proj16_kernel(
        const uint32_t* __restrict__ W16, const float* __restrict__ bias,
        const float* __restrict__ Xf, int src_half,
        float* __restrict__ Yf, int dst_half) {
    extern __shared__ uint32_t ps[];
    uint32_t* Ws2 = ps;
    uint32_t* Xs2 = ps + 192 * PJP2;
    float*    fbuf = (float*)ps;

    int tid  = threadIdx.x;
    int lane = tid & 31;
    int warp = tid >> 5;
    int g    = lane >> 2;
    int tg   = lane & 3;
    int wm   = warp >> 2;
    int wn   = warp & 3;

    int b  = blockIdx.z;
    int t0 = blockIdx.x * 128;
    const float* Xb = Xf + (size_t)b * D * T;
    const __half* Ab = g_attn16 + (size_t)b * T * D;

    uint32_t sb = smem_addr32(ps);

    #pragma unroll
    for (int it = 0; it < 9; it++) {
        int i = tid + it * 512;
        int o = i / 24, c = i % 24;
        cpasync16(sb + 4u * (o * PJP2 + c * 4), W16 + o * 96 + c * 4);
    }
    if (src_half == 0) {
        #pragma unroll
        for (int it = 0; it < 6; it++) {
            int i = tid + it * 512;
            int k2 = i >> 5, t4 = i & 31;
            float4 xa = *(const float4*)(Xb + (size_t)(2 * k2)     * T + t0 + t4 * 4);
            float4 xb = *(const float4*)(Xb + (size_t)(2 * k2 + 1) * T + t0 + t4 * 4);
            Xs2[(t4 * 4 + 0) * PJP2 + k2] = h2bits(xa.x, xb.x);
            Xs2[(t4 * 4 + 1) * PJP2 + k2] = h2bits(xa.y, xb.y);
            Xs2[(t4 * 4 + 2) * PJP2 + k2] = h2bits(xa.z, xb.z);
            Xs2[(t4 * 4 + 3) * PJP2 + k2] = h2bits(xa.w, xb.w);
        }
    } else {
        #pragma unroll
        for (int it = 0; it < 6; it++) {
            int i = tid + it * 512;
            int t = i / 24, c = i % 24;
            cpasync16(sb + 4u * (192 * PJP2 + t * PJP2 + c * 4),
                      Ab + (size_t)(t0 + t) * D + c * 8);
        }
    }
    cp_commit();
    cp_wait_all();
    __syncthreads();

    int a_row = lane & 15;
    int a_kw  = 4 * ((lane >> 4) & 1);
    int b_row = 8 * ((lane >> 4) & 1) + (lane & 7);
    int b_kw  = 4 * ((lane >> 3) & 1);

    uint32_t xa_addr[2], wb_addr[3];
    #pragma unroll
    for (int mt = 0; mt < 2; mt++)
        xa_addr[mt] = sb + 4 * (192 * PJP2 + (wm * 32 + mt * 16 + a_row) * PJP2 + a_kw);
    #pragma unroll
    for (int np = 0; np < 3; np++)
        wb_addr[np] = sb + 4 * ((wn * 48 + np * 16 + b_row) * PJP2 + b_kw);

    float acc[2][6][4];
    #pragma unroll
    for (int mt = 0; mt < 2; mt++)
        #pragma unroll
        for (int nt = 0; nt < 6; nt++)
            #pragma unroll
            for (int c = 0; c < 4; c++) acc[mt][nt][c] = 0.f;

    #pragma unroll
    for (int ks = 0; ks < 12; ks++) {
        uint32_t koff = ks * 32;
        uint32_t aX[2][4], bw[3][4];
        #pragma unroll
        for (int mt = 0; mt < 2; mt++) ldmx4(aX[mt], xa_addr[mt] + koff);
        #pragma unroll
        for (int np = 0; np < 3; np++) ldmx4(bw[np], wb_addr[np] + koff);
        #pragma unroll
        for (int mt = 0; mt < 2; mt++)
            #pragma unroll
            for (int np = 0; np < 3; np++) {
                mma16(acc[mt][np * 2],     aX[mt], bw[np][0], bw[np][1]);
                mma16(acc[mt][np * 2 + 1], aX[mt], bw[np][2], bw[np][3]);
            }
    }

    if (dst_half) {
        #pragma unroll
        for (int mt = 0; mt < 2; mt++) {
            int t_lo = wm * 32 + mt * 16 + g;
            int t_hi = t_lo + 8;
            #pragma unroll
            for (int nt = 0; nt < 6; nt++) {
                int o0 = wn * 48 + nt * 8 + 2 * tg;
                float b0v = bias[o0], b1v = bias[o0 + 1];
                *(uint32_t*)&g_q16[((size_t)b * T + t0 + t_lo) * D + o0] =
                    h2bits(acc[mt][nt][0] + b0v, acc[mt][nt][1] + b1v);
                *(uint32_t*)&g_q16[((size_t)b * T + t0 + t_hi) * D + o0] =
                    h2bits(acc[mt][nt][2] + b0v, acc[mt][nt][3] + b1v);
            }
        }
    } else {
        __syncthreads();
        #pragma unroll
        for (int mt = 0; mt < 2; mt++) {
            int t_lo = wm * 32 + mt * 16 + g;
            int t_hi = t_lo + 8;
            #pragma unroll
            for (int nt = 0; nt < 6; nt++) {
                int o0 = wn * 48 + nt * 8 + 2 * tg;
                float b0v = bias[o0], b1v = bias[o0 + 1];
                fbuf[(o0)     * FBP + t_lo] = acc[mt][nt][0] + b0v;
                fbuf[(o0 + 1) * FBP + t_lo] = acc[mt][nt][1] + b1v;
                fbuf[(o0)     * FBP + t_hi] = acc[mt][nt][2] + b0v;
                fbuf[(o0 + 1) * FBP + t_hi] = acc[mt][nt][3] + b1v;
            }
        }
        __syncthreads();
        #pragma unroll
        for (int it = 0; it < 12; it++) {
            int i = tid + it * 512;
            int o = i >> 5, t4 = i & 31;
            float4 v = *(float4*)&fbuf[o * FBP + t4 * 4];
            *(float4*)(Yf + ((size_t)b * D + o) * T + t0 + t4 * 4) = v;
        }
    }
}

// ---------------------------------------------------------------------------
// Kernel 3: fp16 mma.sync attention. 128-query tile, SCH=64, 256 threads,
// 100.3 KB SMEM -> 2 CTAs/SM (fixes wave quantization, 1024 CTAs = 6.92
// waves; independent CTAs interleave softmax with the other CTA's HMMA).
// 8 warps: wqi=warp>>1 owns 32 q rows; wsi=warp&1 owns s-half (QK) / dk-half (PV).
// SMEM (h2 words): Q[128][52], K[2][64][52], V[2][96][36], P[128][36], l[256].
// ---------------------------------------------------------------------------
#define QROWS 128
#define SCH   64
#define QP2   52
#define KP2   52
#define VP2   36
#define PP2   36
#define KSZ   (SCH * KP2)              // 3328
#define VSZ   (DKH * VP2)              // 3456
#define OQ2   0
#define OK2   (QROWS * QP2)            // 6656 (buf0); buf1 at +KSZ
#define OV2   (OK2 + 2 * KSZ)          // 13312 (buf0); buf1 at +VSZ
#define OP2   (OV2 + 2 * VSZ)          // 20224
#define OL2   (OP2 + QROWS * PP2)      // 24832
#define SMEM_ATTN_BYTES ((OL2 + 2 * QROWS) * 4)   // 100352

#define NCHUNK 16

__global__ void __launch_bounds__(256, 2) attn_mma_kernel() {
    extern __shared__ uint32_t sh2[];
    float* lsh = (float*)(sh2 + OL2);

    int tid  = threadIdx.x;
    int lane = tid & 31;
    int warp = tid >> 5;
    int g    = lane >> 2;
    int tg   = lane & 3;
    int wqi  = warp >> 1;   // 0..3
    int wsi  = warp & 1;
    int wq   = wqi * 32;
    int bar_id = 1 + wqi;   // named barrier per q-pair (ids 1..4)

    int t0 = blockIdx.x * QROWS;
    int h  = blockIdx.y;
    int b  = blockIdx.z;

    uint32_t sb = smem_addr32(sh2);
    const __half* kb = g_k16T + (size_t)h * BANK * DKH;
    const __half* vb = g_v16 + (size_t)h * DKH * BANK;

    // ---- Prefetch K/V for a chunk via cp.async (zero-filled tail) ----
    auto stage_kv = [&](int cin) {
        int s0c2 = cin * SCH;
        int valid2 = BANK - s0c2; if (valid2 > SCH) valid2 = SCH;   // 64 or 40
        uint32_t kdst = sb + 4u * (OK2 + (cin & 1) * KSZ);
        uint32_t vdst = sb + 4u * (OV2 + (cin & 1) * VSZ);
        #pragma unroll
        for (int it = 0; it < 3; it++) {
            int i = tid + it * 256;
            int row = i / 12, c = i % 12;
            int ok = row < valid2;
            const __half* src = kb + (size_t)(s0c2 + (ok ? row : 0)) * DKH + c * 8;
            cpasync16z(kdst + 4u * (row * KP2 + c * 4), src, ok ? 16 : 0);
        }
        #pragma unroll
        for (int it = 0; it < 3; it++) {
            int i = tid + it * 256;
            int row = i >> 3, c = i & 7;
            int ok = (c * 8 + 8) <= valid2;
            const __half* src = vb + (size_t)row * BANK + s0c2 + (ok ? c * 8 : 0);
            cpasync16z(vdst + 4u * (row * VP2 + c * 4), src, ok ? 16 : 0);
        }
        cp_commit();
    };

    stage_kv(0);
    const __half* qb = g_q16 + ((size_t)b * T + t0) * D + h * DKH;
    #pragma unroll
    for (int it = 0; it < 6; it++) {
        int i = tid + it * 256;
        int q = i / 12, c = i % 12;
        uint4 v = *(const uint4*)(qb + (size_t)q * D + c * 8);
        *(uint4*)&sh2[OQ2 + q * QP2 + c * 4] = v;
    }

    int a_row  = lane & 15;
    int a_kw   = 4 * ((lane >> 4) & 1);
    int b_row  = 8 * ((lane >> 4) & 1) + (lane & 7);
    int b_kw   = 4 * ((lane >> 3) & 1);
    int st_row = 8 * ((lane >> 3) & 1) + (lane & 7);
    int st_cw  = 4 * ((lane >> 4) & 1);

    uint32_t qa_addr[2], pa_addr[2], ps_addr[2];
    #pragma unroll
    for (int mt = 0; mt < 2; mt++) {
        qa_addr[mt] = sb + 4 * (OQ2 + (wq + mt * 16 + a_row)  * QP2 + a_kw);
        pa_addr[mt] = sb + 4 * (OP2 + (wq + mt * 16 + a_row)  * PP2 + a_kw);
        ps_addr[mt] = sb + 4 * (OP2 + (wq + mt * 16 + st_row) * PP2 + st_cw);
    }
    uint32_t kb_addr0 = sb + 4 * (OK2 + (wsi * 32 + b_row) * KP2 + b_kw);
    uint32_t vb_addr0 = sb + 4 * (OV2 + (wsi * 48 + b_row) * VP2 + b_kw);

    float o[2][6][4];
    #pragma unroll
    for (int mt = 0; mt < 2; mt++)
        #pragma unroll
        for (int nt = 0; nt < 6; nt++)
            #pragma unroll
            for (int c = 0; c < 4; c++) o[mt][nt][c] = 0.f;
    float lsum[2][2] = {{0.f, 0.f}, {0.f, 0.f}};

    for (int ci = 0; ci < NCHUNK; ci++) {
        uint32_t kbuf = kb_addr0 + 4u * ((ci & 1) * KSZ);
        uint32_t vbuf = vb_addr0 + 4u * ((ci & 1) * VSZ);

        cp_wait_all();
        __syncthreads();   // K/V(ci) ready; all PV(ci-1) complete

        if (ci < NCHUNK - 1) stage_kv(ci + 1);

        // ---- QK: this warp's 32 s-cols (wsi half of 64) ----
        float sc[2][4][4];
        #pragma unroll
        for (int mt = 0; mt < 2; mt++)
            #pragma unroll
            for (int nt = 0; nt < 4; nt++)
                #pragma unroll
                for (int c = 0; c < 4; c++) sc[mt][nt][c] = 0.f;

        #pragma unroll
        for (int ks = 0; ks < 6; ks++) {
            uint32_t koff = ks * 32;
            uint32_t aQ[2][4];
            ldmx4(aQ[0], qa_addr[0] + koff);
            ldmx4(aQ[1], qa_addr[1] + koff);
            #pragma unroll
            for (int np = 0; np < 2; np++) {
                uint32_t bk4[4];
                ldmx4(bk4, kbuf + 4 * (uint32_t)(np * 16 * KP2) + koff);
                mma16(sc[0][np * 2],     aQ[0], bk4[0], bk4[1]);
                mma16(sc[0][np * 2 + 1], aQ[0], bk4[2], bk4[3]);
                mma16(sc[1][np * 2],     aQ[1], bk4[0], bk4[1]);
                mma16(sc[1][np * 2 + 1], aQ[1], bk4[2], bk4[3]);
            }
        }

        // ---- Softmax (no max); mask only the final half-chunk tail ----
        if (ci == NCHUNK - 1 && wsi == 1) {
            #pragma unroll
            for (int mt = 0; mt < 2; mt++) {
                #pragma unroll
                for (int nt = 0; nt < 4; nt++) {
                    int sg = (NCHUNK - 1) * SCH + 32 + nt * 8 + 2 * tg;
                    float p0 = (sg     < BANK) ? ex2f(sc[mt][nt][0]) : 0.f;
                    float p1 = (sg + 1 < BANK) ? ex2f(sc[mt][nt][1]) : 0.f;
                    float p2 = (sg     < BANK) ? ex2f(sc[mt][nt][2]) : 0.f;
                    float p3 = (sg + 1 < BANK) ? ex2f(sc[mt][nt][3]) : 0.f;
                    lsum[mt][0] += p0 + p1;
                    lsum[mt][1] += p2 + p3;
                    sc[mt][nt][0] = p0; sc[mt][nt][1] = p1;
                    sc[mt][nt][2] = p2; sc[mt][nt][3] = p3;
                }
            }
        } else {
            #pragma unroll
            for (int mt = 0; mt < 2; mt++) {
                #pragma unroll
                for (int nt = 0; nt < 4; nt++) {
                    float p0 = ex2f(sc[mt][nt][0]);
                    float p1 = ex2f(sc[mt][nt][1]);
                    float p2 = ex2f(sc[mt][nt][2]);
                    float p3 = ex2f(sc[mt][nt][3]);
                    lsum[mt][0] += p0 + p1;
                    lsum[mt][1] += p2 + p3;
                    sc[mt][nt][0] = p0; sc[mt][nt][1] = p1;
                    sc[mt][nt][2] = p2; sc[mt][nt][3] = p3;
                }
            }
        }
        #pragma unroll
        for (int mt = 0; mt < 2; mt++) {
            #pragma unroll
            for (int np = 0; np < 2; np++) {
                stmx4(ps_addr[mt] + 4 * (uint32_t)(wsi * 16 + np * 8),
                      h2bits(sc[mt][np * 2][0],     sc[mt][np * 2][1]),
                      h2bits(sc[mt][np * 2][2],     sc[mt][np * 2][3]),
                      h2bits(sc[mt][np * 2 + 1][0], sc[mt][np * 2 + 1][1]),
                      h2bits(sc[mt][np * 2 + 1][2], sc[mt][np * 2 + 1][3]));
            }
        }
        bar_pair(bar_id);   // P complete within this q-pair

        // ---- PV: O[q][dk_half] += P[q][s] * V[dk][s] over full 64-s chunk ----
        #pragma unroll
        for (int ks = 0; ks < 4; ks++) {
            uint32_t koff = ks * 32;
            uint32_t aP[2][4];
            ldmx4(aP[0], pa_addr[0] + koff);
            ldmx4(aP[1], pa_addr[1] + koff);
            #pragma unroll
            for (int np = 0; np < 3; np++) {
                uint32_t bv4[4];
                ldmx4(bv4, vbuf + 4 * (uint32_t)(np * 16 * VP2) + koff);
                mma16(o[0][np * 2],     aP[0], bv4[0], bv4[1]);
                mma16(o[0][np * 2 + 1], aP[0], bv4[2], bv4[3]);
                mma16(o[1][np * 2],     aP[1], bv4[0], bv4[1]);
                mma16(o[1][np * 2 + 1], aP[1], bv4[2], bv4[3]);
            }
        }
    }

    // ---- Reduce l within quad, publish per-half, combine across pair ----
    #pragma unroll
    for (int mt = 0; mt < 2; mt++)
        #pragma unroll
        for (int j = 0; j < 2; j++) {
            float v = lsum[mt][j];
            v += __shfl_xor_sync(0xFFFFFFFF, v, 1);
            v += __shfl_xor_sync(0xFFFFFFFF, v, 2);
            lsum[mt][j] = v;
        }
    __syncthreads();
    if (tg == 0) {
        #pragma unroll
        for (int mt = 0; mt < 2; mt++) {
            lsh[wsi * QROWS + wq + mt * 16 + g]     = lsum[mt][0];
            lsh[wsi * QROWS + wq + mt * 16 + g + 8] = lsum[mt][1];
        }
    }
    __syncthreads();

    float inv[2][2];
    #pragma unroll
    for (int mt = 0; mt < 2; mt++) {
        int q_lo = wq + mt * 16 + g;
        inv[mt][0] = 1.f / (lsh[q_lo]     + lsh[QROWS + q_lo]);
        inv[mt][1] = 1.f / (lsh[q_lo + 8] + lsh[QROWS + q_lo + 8]);
    }

    __half* ob = g_attn16 + ((size_t)b * T + t0) * D + h * DKH;
    #pragma unroll
    for (int mt = 0; mt < 2; mt++) {
        int q_lo = wq + mt * 16 + g;
        int q_hi = q_lo + 8;
        #pragma unroll
        for (int nt = 0; nt < 6; nt++) {
            int dk = wsi * 48 + nt * 8 + 2 * tg;
            *(uint32_t*)(ob + (size_t)q_lo * D + dk) =
                h2bits(o[mt][nt][0] * inv[mt][0], o[mt][nt][1] * inv[mt][0]);
            *(uint32_t*)(ob + (size_t)q_hi * D + dk) =
                h2bits(o[mt][nt][2] * inv[mt][1], o[mt][nt][3] * inv[mt][1]);
        }
    }
}

// ---------------------------------------------------------------------------
extern "C" void kernel_launch(void* const* d_in, const int* in_sizes, int n_in,
                              void* d_out, int out_size) {
    const float* z  = (const float*)d_in[0];
    const float* mb = (const float*)d_in[1];
    const float* Wq = (const float*)d_in[2];
    const float* bq = (const float*)d_in[3];
    const float* Wk = (const float*)d_in[4];
    const float* bk = (const float*)d_in[5];
    const float* Wv = (const float*)d_in[6];
    const float* bv = (const float*)d_in[7];
    const float* Wo = (const float*)d_in[8];
    const float* bo = (const float*)d_in[9];
    float* out = (float*)d_out;

    const float alpha_q = 1.4426950408889634f / sqrtf(96.0f);

    // 0. Weight prep (fp16 conversion, alpha folded into Wq/bq)
    wprep_kernel<<<2, 256>>>(Wq, bq, Wo, alpha_q);

    // 1. K/V projection (batch-independent) -> fp16
    kv_proj_kernel<<<dim3(4, 24, 2), 256>>>(mb, Wk, bk, Wv, bv);

    uint32_t *dWq16, *dWo16; float* dbq;
    cudaGetSymbolAddress((void**)&dWq16, g_Wq16);
    cudaGetSymbolAddress((void**)&dWo16, g_Wo16);
    cudaGetSymbolAddress((void**)&dbq,  g_bq);

    // 2. Q projection -> g_q16 [b][t][d] fp16
    cudaFuncSetAttribute(proj16_kernel,
                         cudaFuncAttributeMaxDynamicSharedMemorySize, SMEM_PROJ_BYTES);
    proj16_kernel<<<dim3(32, 1, 16), 512, SMEM_PROJ_BYTES>>>(
        dWq16, dbq, z, 0, nullptr, 1);

    // 3. fp16 mma.sync attention (2 CTAs/SM, 1024 CTAs) -> g_attn16
    cudaFuncSetAttribute(attn_mma_kernel,
                         cudaFuncAttributeMaxDynamicSharedMemorySize, SMEM_ATTN_BYTES);
    attn_mma_kernel<<<dim3(T / QROWS, NH, B), 256, SMEM_ATTN_BYTES>>>();

    // 4. Output projection -> d_out fp32 [b][d][t]
    proj16_kernel<<<dim3(32, 1, 16), 512, SMEM_PROJ_BYTES>>>(
        dWo16, bo, nullptr, 1, out, 0);
}